// round 1
// baseline (speedup 1.0000x reference)
#include <cuda_runtime.h>

// QLayer analytic form:
//   Circuit = per-wire RX(x_w) RY(x_w) RZ(theta_w) on |0>, then CNOT ladder
//   0->1, 1->2, ..., 14->15, then measure Z on every wire.
//
//   Per-wire <Z> after RZ*RY*RX|0> = cos^2(x_w)  (RZ diagonal, doesn't matter).
//   Heisenberg: Z_w pulled back through the CNOT ladder becomes Z_0 Z_1 ... Z_w.
//   Product state  =>  out[b][w] = prod_{j<=w} cos^2(x[b][j]).
//
// 512 x 16 output = 8192 elements. One thread per element; inclusive prefix
// product over 16-lane segments via shfl_up (2 rows per warp).

#define NQ   16
#define BATCH 512

__global__ void qlayer_kernel(const float* __restrict__ x,
                              float* __restrict__ out)
{
    int idx = blockIdx.x * blockDim.x + threadIdx.x;   // 0 .. 8191
    int lane = threadIdx.x & 31;
    int seg_lane = lane & 15;                          // position within 16-wire row

    // Coalesced load: idx maps directly to row-major (b, w).
    float xv = x[idx];
    float cc = cosf(xv);
    float v = cc * cc;

    // Inclusive prefix product over the 16-lane segment.
    #pragma unroll
    for (int off = 1; off < 16; off <<= 1) {
        float o = __shfl_up_sync(0xffffffffu, v, off);
        if (seg_lane >= off) v *= o;
    }

    out[idx] = v;
}

extern "C" void kernel_launch(void* const* d_in, const int* in_sizes, int n_in,
                              void* d_out, int out_size)
{
    const float* x = (const float*)d_in[0];
    // d_in[1] = params (RZ angles) — analytically irrelevant to <Z>.
    float* out = (float*)d_out;

    const int total = BATCH * NQ;          // 8192
    const int threads = 256;
    qlayer_kernel<<<total / threads, threads>>>(x, out);
}